// round 16
// baseline (speedup 1.0000x reference)
#include <cuda_runtime.h>
#include <cuda_bf16.h>
#include <math_constants.h>
#include <cstdint>

// Problem constants (fixed by dataset)
#define NN     50000
#define EE     800000
#define GG     512
#define IN_DIM 16
#define EDGE_DIM 8
#define HIDC   32
#define OUTD   64
#define HEADS  4
#define D2     (HEADS*HIDC)   // 128

#define SCAN_BLK 1024
#define SCAN_NB  ((NN + SCAN_BLK - 1) / SCAN_BLK)   // 49

typedef unsigned long long u64;

// ---- packed f32x2 helpers (Blackwell: fma.rn.f32x2 etc.) ----
__device__ __forceinline__ u64 pk2(float a, float b) {
    u64 r; asm("mov.b64 %0, {%1, %2};" : "=l"(r) : "f"(a), "f"(b)); return r;
}
__device__ __forceinline__ void upk2(u64 v, float& a, float& b) {
    asm("mov.b64 {%0, %1}, %2;" : "=f"(a), "=f"(b) : "l"(v));
}
__device__ __forceinline__ u64 fma2_(u64 a, u64 b, u64 c) {
    u64 r; asm("fma.rn.f32x2 %0, %1, %2, %3;" : "=l"(r) : "l"(a), "l"(b), "l"(c)); return r;
}
__device__ __forceinline__ u64 add2_(u64 a, u64 b) {
    u64 r; asm("add.rn.f32x2 %0, %1, %2;" : "=l"(r) : "l"(a), "l"(b)); return r;
}
__device__ __forceinline__ u64 mul2_(u64 a, u64 b) {
    u64 r; asm("mul.rn.f32x2 %0, %1, %2;" : "=l"(r) : "l"(a), "l"(b)); return r;
}
__device__ __forceinline__ u64 abs2_(u64 a) {
    u64 r; asm("and.b64 %0, %1, %2;" : "=l"(r) : "l"(a), "l"(0x7FFFFFFF7FFFFFFFULL)); return r;
}

// ---------------- device scratch ----------------
__device__ float g_xs[NN * D2];
__device__ float g_xd[NN * D2];
__device__ float g_h1[NN * D2];
__device__ float g_h2[NN * D2];
__device__ float g_h3[NN * HIDC];
__device__ float g_escore[EE * HEADS];   // [eid][h] (float4 per edge when H=4)
__device__ int   g_deg[NN];
__device__ int   g_tmp[SCAN_NB * SCAN_BLK];
__device__ int   g_rowptr[NN + 1];
__device__ int   g_wp[NN];
__device__ int   g_blksum[SCAN_NB + 1];
__device__ int2  g_csr[EE];              // (src, eid) per csr slot
__device__ float g_sums[GG * HIDC];
__device__ float g_cnt[GG];

// ---------------- CSR build ----------------
__global__ void zero_kernel() {
    int i = blockIdx.x * blockDim.x + threadIdx.x;
    if (i < NN) g_deg[i] = 0;
    if (i < GG * HIDC) g_sums[i] = 0.f;
    if (i < GG) g_cnt[i] = 0.f;
}

__global__ void hist_kernel(const int* __restrict__ dst) {
    int e = blockIdx.x * blockDim.x + threadIdx.x;
    if (e < EE) atomicAdd(&g_deg[dst[e]], 1);
}

__global__ void scan1_kernel() {
    __shared__ int sm[SCAN_BLK];
    int tid = threadIdx.x;
    int i = blockIdx.x * SCAN_BLK + tid;
    int v = (i < NN) ? g_deg[i] : 0;
    sm[tid] = v;
    __syncthreads();
    for (int o = 1; o < SCAN_BLK; o <<= 1) {
        int t = (tid >= o) ? sm[tid - o] : 0;
        __syncthreads();
        sm[tid] += t;
        __syncthreads();
    }
    g_tmp[blockIdx.x * SCAN_BLK + tid] = sm[tid] - v;
    if (tid == SCAN_BLK - 1) g_blksum[blockIdx.x] = sm[tid];
}

// scan3 folds the cross-block prefix (each 256-block sits inside one 1024-chunk)
__global__ void scan3_kernel() {
    __shared__ int s_off;
    int blk = (blockIdx.x * 256) / SCAN_BLK;
    if (threadIdx.x == 0) {
        int run = 0;
        for (int b = 0; b < blk; b++) run += g_blksum[b];
        s_off = run;
    }
    __syncthreads();
    int i = blockIdx.x * 256 + threadIdx.x;
    if (i < NN) {
        int v = g_tmp[i] + s_off;
        g_rowptr[i] = v;
        g_wp[i] = v;
    }
    if (i == 0) g_rowptr[NN] = EE;
}

__global__ void scatter_kernel(const int* __restrict__ src, const int* __restrict__ dst) {
    int e = blockIdx.x * blockDim.x + threadIdx.x;
    if (e < EE) {
        int d = dst[e];
        int pos = atomicAdd(&g_wp[d], 1);
        g_csr[pos] = make_int2(src[e], e);
    }
}

// ---------------- node linear (packed f32x2, padded smem) ----------------
template<int DIN, int DOUT, int TN>
__global__ __launch_bounds__(DOUT) void node_linear_kernel(
        const float* __restrict__ x,
        const float* __restrict__ Ws, const float* __restrict__ Wd,
        const float* __restrict__ bs, const float* __restrict__ bd,
        float* __restrict__ xs, float* __restrict__ xd) {
    __shared__ float xsm[DIN][TN + 2];
    const int n0 = blockIdx.x * TN;
    const int tid = threadIdx.x;
    for (int i = tid; i < TN * DIN; i += DOUT) {
        int t = i / DIN, k = i - t * DIN;
        int n = n0 + t;
        xsm[k][t] = (n < NN) ? x[n * DIN + k] : 0.f;
    }
    __syncthreads();

    u64 accs[TN / 2], accd[TN / 2];
#pragma unroll
    for (int p = 0; p < TN / 2; p++) { accs[p] = 0ull; accd[p] = 0ull; }

#pragma unroll 4
    for (int k = 0; k < DIN; k++) {
        float wsv = __ldg(Ws + k * DOUT + tid);
        float wdv = __ldg(Wd + k * DOUT + tid);
        u64 ws2 = pk2(wsv, wsv);
        u64 wd2 = pk2(wdv, wdv);
        const u64* xp = reinterpret_cast<const u64*>(&xsm[k][0]);
#pragma unroll
        for (int p = 0; p < TN / 2; p++) {
            u64 xv = xp[p];
            accs[p] = fma2_(xv, ws2, accs[p]);
            accd[p] = fma2_(xv, wd2, accd[p]);
        }
    }
    float bsv = __ldg(bs + tid), bdv = __ldg(bd + tid);
#pragma unroll
    for (int p = 0; p < TN / 2; p++) {
        float s_lo, s_hi, d_lo, d_hi;
        upk2(accs[p], s_lo, s_hi);
        upk2(accd[p], d_lo, d_hi);
        int n = n0 + 2 * p;
        if (n < NN) {
            xs[n * DOUT + tid] = s_lo + bsv;
            xd[n * DOUT + tid] = d_lo + bdv;
        }
        if (n + 1 < NN) {
            xs[(n + 1) * DOUT + tid] = s_hi + bsv;
            xd[(n + 1) * DOUT + tid] = d_hi + bdv;
        }
    }
}

// ---------------- GATv2 scores: warp per edge PAIR, packed f32x2 math (FROZEN) ----------------
__global__ __launch_bounds__(128, 5) void gat_score4_kernel(
        const float* __restrict__ xs, const float* __restrict__ xd,
        const int* __restrict__ esrc, const int* __restrict__ edst,
        const float* __restrict__ eattr,
        const float* __restrict__ We, const float* __restrict__ att,
        float* __restrict__ escore) {
    __shared__ float sWe[EDGE_DIM * D2];
    for (int i = threadIdx.x; i < EDGE_DIM * D2; i += 128) sWe[i] = We[i];
    __syncthreads();

    int lane = threadIdx.x & 31;
    int g = lane >> 3;          // head
    int q = lane & 7;           // channel quad
    int col0 = g * 32 + q * 4;

    u64 we2[2][EDGE_DIM];
    u64 att2[2];
#pragma unroll
    for (int p = 0; p < 2; p++) {
#pragma unroll
        for (int k = 0; k < EDGE_DIM; k++)
            we2[p][k] = pk2(sWe[k * D2 + col0 + 2 * p], sWe[k * D2 + col0 + 2 * p + 1]);
        att2[p] = pk2(__ldg(att + col0 + 2 * p), __ldg(att + col0 + 2 * p + 1));
    }
    const u64 C06 = pk2(0.6f, 0.6f);
    const u64 C04 = pk2(0.4f, 0.4f);

    int warpId = (blockIdx.x * 128 + threadIdx.x) >> 5;
    int stride = (gridDim.x * 128) >> 5;
    int step = 2 * stride;

    int e0 = warpId, e1 = warpId + stride;
    int s0 = 0, d0 = 0, s1 = 0, d1 = 0;
    if (e0 < EE) { s0 = __ldg(esrc + e0); d0 = __ldg(edst + e0); }
    if (e1 < EE) { s1 = __ldg(esrc + e1); d1 = __ldg(edst + e1); }

    while (e0 < EE) {
        bool v1 = (e1 < EE);
        const float4* ap0 = reinterpret_cast<const float4*>(eattr + e0 * EDGE_DIM);
        float4 a00 = __ldg(ap0), a01 = __ldg(ap0 + 1);
        float4 xs0 = __ldg(reinterpret_cast<const float4*>(xs + s0 * D2 + col0));
        float4 xd0 = __ldg(reinterpret_cast<const float4*>(xd + d0 * D2 + col0));
        float4 a10 = make_float4(0,0,0,0), a11 = a10, xs1 = a10, xd1 = a10;
        if (v1) {
            const float4* ap1 = reinterpret_cast<const float4*>(eattr + e1 * EDGE_DIM);
            a10 = __ldg(ap1); a11 = __ldg(ap1 + 1);
            xs1 = __ldg(reinterpret_cast<const float4*>(xs + s1 * D2 + col0));
            xd1 = __ldg(reinterpret_cast<const float4*>(xd + d1 * D2 + col0));
        }
        int ne0 = e0 + step, ne1 = e1 + step;
        int ns0 = 0, nd0 = 0, ns1 = 0, nd1 = 0;
        if (ne0 < EE) { ns0 = __ldg(esrc + ne0); nd0 = __ldg(edst + ne0); }
        if (ne1 < EE) { ns1 = __ldg(esrc + ne1); nd1 = __ldg(edst + ne1); }

        // edge 0 (packed)
        {
            u64 ak[8] = { pk2(a00.x,a00.x), pk2(a00.y,a00.y), pk2(a00.z,a00.z), pk2(a00.w,a00.w),
                          pk2(a01.x,a01.x), pk2(a01.y,a01.y), pk2(a01.z,a01.z), pk2(a01.w,a01.w) };
            u64 xsp[2] = { pk2(xs0.x, xs0.y), pk2(xs0.z, xs0.w) };
            u64 xdp[2] = { pk2(xd0.x, xd0.y), pk2(xd0.z, xd0.w) };
            u64 sc2 = 0ull;
#pragma unroll
            for (int p = 0; p < 2; p++) {
                u64 ea2 = mul2_(ak[0], we2[p][0]);
#pragma unroll
                for (int k = 1; k < EDGE_DIM; k++) ea2 = fma2_(ak[k], we2[p][k], ea2);
                u64 z2 = add2_(add2_(xsp[p], xdp[p]), ea2);
                u64 r2 = fma2_(z2, C06, mul2_(abs2_(z2), C04));
                sc2 = fma2_(r2, att2[p], sc2);
            }
            float lo, hi; upk2(sc2, lo, hi);
            float pr = lo + hi;
            pr += __shfl_xor_sync(0xffffffffu, pr, 4);
            pr += __shfl_xor_sync(0xffffffffu, pr, 2);
            pr += __shfl_xor_sync(0xffffffffu, pr, 1);
            if (q == 0) escore[e0 * 4 + g] = pr;
        }
        // edge 1 (independent chain)
        if (v1) {
            u64 ak[8] = { pk2(a10.x,a10.x), pk2(a10.y,a10.y), pk2(a10.z,a10.z), pk2(a10.w,a10.w),
                          pk2(a11.x,a11.x), pk2(a11.y,a11.y), pk2(a11.z,a11.z), pk2(a11.w,a11.w) };
            u64 xsp[2] = { pk2(xs1.x, xs1.y), pk2(xs1.z, xs1.w) };
            u64 xdp[2] = { pk2(xd1.x, xd1.y), pk2(xd1.z, xd1.w) };
            u64 sc2 = 0ull;
#pragma unroll
            for (int p = 0; p < 2; p++) {
                u64 ea2 = mul2_(ak[0], we2[p][0]);
#pragma unroll
                for (int k = 1; k < EDGE_DIM; k++) ea2 = fma2_(ak[k], we2[p][k], ea2);
                u64 z2 = add2_(add2_(xsp[p], xdp[p]), ea2);
                u64 r2 = fma2_(z2, C06, mul2_(abs2_(z2), C04));
                sc2 = fma2_(r2, att2[p], sc2);
            }
            float lo, hi; upk2(sc2, lo, hi);
            float pr = lo + hi;
            pr += __shfl_xor_sync(0xffffffffu, pr, 4);
            pr += __shfl_xor_sync(0xffffffffu, pr, 2);
            pr += __shfl_xor_sync(0xffffffffu, pr, 1);
            if (q == 0) escore[e1 * 4 + g] = pr;
        }

        e0 = ne0; e1 = ne1;
        s0 = ns0; d0 = nd0; s1 = ns1; d1 = nd1;
    }
}

// H=1: 4 edges per warp, pipelined src/dst prefetch, folded leaky
__global__ __launch_bounds__(128) void gat_score1_kernel(
        const float* __restrict__ xs, const float* __restrict__ xd,
        const int* __restrict__ esrc, const int* __restrict__ edst,
        const float* __restrict__ eattr,
        const float* __restrict__ We, const float* __restrict__ att,
        float* __restrict__ escore) {
    int lane = threadIdx.x & 31;
    int g = lane >> 3;
    int q = lane & 7;
    int col0 = q * 4;

    float we_r[4][EDGE_DIM];
    float a06[4], a04[4];
#pragma unroll
    for (int c = 0; c < 4; c++) {
#pragma unroll
        for (int k = 0; k < EDGE_DIM; k++) we_r[c][k] = __ldg(We + k * HIDC + col0 + c);
        float av = __ldg(att + col0 + c);
        a06[c] = 0.6f * av;
        a04[c] = 0.4f * av;
    }

    int warpId = (blockIdx.x * 128 + threadIdx.x) >> 5;
    int nWarps = (gridDim.x * 128) >> 5;
    int step = nWarps * 4;

    int eb = warpId * 4;
    int e = eb + g;
    int s = 0, d = 0;
    if (e < EE) { s = __ldg(esrc + e); d = __ldg(edst + e); }

    while (eb < EE) {
        bool valid = (e < EE);
        float4 a0 = make_float4(0,0,0,0), a1 = a0, xsv = a0, xdv = a0;
        if (valid) {
            const float4* ap = reinterpret_cast<const float4*>(eattr + e * EDGE_DIM);
            a0 = __ldg(ap); a1 = __ldg(ap + 1);
            xsv = __ldg(reinterpret_cast<const float4*>(xs + s * HIDC + col0));
            xdv = __ldg(reinterpret_cast<const float4*>(xd + d * HIDC + col0));
        }
        int neb = eb + step;
        int ne = neb + g;
        int ns = 0, nd = 0;
        if (ne < EE) { ns = __ldg(esrc + ne); nd = __ldg(edst + ne); }

        if (valid) {
            const float* xsa = &xsv.x;
            const float* xda = &xdv.x;
            float pr = 0.f;
#pragma unroll
            for (int c = 0; c < 4; c++) {
                float ea = a0.x * we_r[c][0] + a0.y * we_r[c][1] + a0.z * we_r[c][2] + a0.w * we_r[c][3]
                         + a1.x * we_r[c][4] + a1.y * we_r[c][5] + a1.z * we_r[c][6] + a1.w * we_r[c][7];
                float z = xsa[c] + xda[c] + ea;
                pr = fmaf(a06[c], z, fmaf(a04[c], fabsf(z), pr));
            }
            pr += __shfl_xor_sync(0xffffffffu, pr, 4);
            pr += __shfl_xor_sync(0xffffffffu, pr, 2);
            pr += __shfl_xor_sync(0xffffffffu, pr, 1);
            if (q == 0) escore[e] = pr;
        }
        eb = neb; e = ne; s = ns; d = nd;
    }
}

// ---------------- softmax + gather: warp per node, float4-row, 4-way unrolled j-loop ----------------
template<bool ELU>
__global__ __launch_bounds__(256) void gat_gather4_kernel(
        const float* __restrict__ xs, const float* __restrict__ escore,
        const float* __restrict__ bias, float* __restrict__ out) {
    __shared__ float s_al[8][32 * 4];   // [warp][j*4 + h]
    __shared__ int   s_src[8][32];
    int wq = threadIdx.x >> 5;
    int n = (blockIdx.x * 256 + threadIdx.x) >> 5;
    int lane = threadIdx.x & 31;
    if (n >= NN) return;
    int s0 = __ldg(&g_rowptr[n]), s1 = __ldg(&g_rowptr[n + 1]);
    int deg = s1 - s0;
    int hsel = lane >> 3;   // head owning my channel quad

    float4 bv = __ldg(reinterpret_cast<const float4*>(bias) + lane);
    float4 acc = make_float4(0.f, 0.f, 0.f, 0.f);

    if (deg > 0 && deg <= 32) {
        float es[HEADS];
        int src = 0;
#pragma unroll
        for (int h = 0; h < HEADS; h++) es[h] = -CUDART_INF_F;
        if (lane < deg) {
            int2 c = g_csr[s0 + lane];
            src = c.x;
            float4 v = __ldg(reinterpret_cast<const float4*>(escore + c.y * 4));
            es[0] = v.x; es[1] = v.y; es[2] = v.z; es[3] = v.w;
        }
        float m[HEADS];
#pragma unroll
        for (int h = 0; h < HEADS; h++) m[h] = es[h];
#pragma unroll
        for (int o = 16; o > 0; o >>= 1)
#pragma unroll
            for (int h = 0; h < HEADS; h++) m[h] = fmaxf(m[h], __shfl_xor_sync(0xffffffffu, m[h], o));
        float p[HEADS], sum[HEADS];
#pragma unroll
        for (int h = 0; h < HEADS; h++) {
            p[h] = (lane < deg) ? __expf(es[h] - m[h]) : 0.f;
            sum[h] = p[h];
        }
#pragma unroll
        for (int o = 16; o > 0; o >>= 1)
#pragma unroll
            for (int h = 0; h < HEADS; h++) sum[h] += __shfl_xor_sync(0xffffffffu, sum[h], o);
        if (lane < deg) {
#pragma unroll
            for (int h = 0; h < HEADS; h++) s_al[wq][lane * 4 + h] = p[h] / sum[h];
            s_src[wq][lane] = src;
        }
        __syncwarp();
        // 4-way unrolled: batch 4 independent LDG.128s before accumulating
        int j = 0;
        for (; j + 4 <= deg; j += 4) {
            float a0 = s_al[wq][(j + 0) * 4 + hsel];
            float a1 = s_al[wq][(j + 1) * 4 + hsel];
            float a2 = s_al[wq][(j + 2) * 4 + hsel];
            float a3 = s_al[wq][(j + 3) * 4 + hsel];
            int sj0 = s_src[wq][j + 0];
            int sj1 = s_src[wq][j + 1];
            int sj2 = s_src[wq][j + 2];
            int sj3 = s_src[wq][j + 3];
            float4 x0 = __ldg(reinterpret_cast<const float4*>(xs + sj0 * D2) + lane);
            float4 x1 = __ldg(reinterpret_cast<const float4*>(xs + sj1 * D2) + lane);
            float4 x2 = __ldg(reinterpret_cast<const float4*>(xs + sj2 * D2) + lane);
            float4 x3 = __ldg(reinterpret_cast<const float4*>(xs + sj3 * D2) + lane);
            acc.x += a0 * x0.x + a1 * x1.x + a2 * x2.x + a3 * x3.x;
            acc.y += a0 * x0.y + a1 * x1.y + a2 * x2.y + a3 * x3.y;
            acc.z += a0 * x0.z + a1 * x1.z + a2 * x2.z + a3 * x3.z;
            acc.w += a0 * x0.w + a1 * x1.w + a2 * x2.w + a3 * x3.w;
        }
        for (; j < deg; j++) {
            float a = s_al[wq][j * 4 + hsel];
            int sj = s_src[wq][j];
            float4 xv = __ldg(reinterpret_cast<const float4*>(xs + sj * D2) + lane);
            acc.x += a * xv.x; acc.y += a * xv.y; acc.z += a * xv.z; acc.w += a * xv.w;
        }
    } else if (deg > 32) {
        float m[HEADS];
#pragma unroll
        for (int h = 0; h < HEADS; h++) m[h] = -CUDART_INF_F;
        for (int i = s0 + lane; i < s1; i += 32) {
            int2 c = g_csr[i];
            float4 v = __ldg(reinterpret_cast<const float4*>(escore + c.y * 4));
            m[0] = fmaxf(m[0], v.x); m[1] = fmaxf(m[1], v.y);
            m[2] = fmaxf(m[2], v.z); m[3] = fmaxf(m[3], v.w);
        }
#pragma unroll
        for (int o = 16; o > 0; o >>= 1)
#pragma unroll
            for (int h = 0; h < HEADS; h++) m[h] = fmaxf(m[h], __shfl_xor_sync(0xffffffffu, m[h], o));
        float sum[HEADS] = {0.f, 0.f, 0.f, 0.f};
        for (int i = s0 + lane; i < s1; i += 32) {
            int2 c = g_csr[i];
            float4 v = __ldg(reinterpret_cast<const float4*>(escore + c.y * 4));
            sum[0] += __expf(v.x - m[0]); sum[1] += __expf(v.y - m[1]);
            sum[2] += __expf(v.z - m[2]); sum[3] += __expf(v.w - m[3]);
        }
#pragma unroll
        for (int o = 16; o > 0; o >>= 1)
#pragma unroll
            for (int h = 0; h < HEADS; h++) sum[h] += __shfl_xor_sync(0xffffffffu, sum[h], o);
        float inv[HEADS];
#pragma unroll
        for (int h = 0; h < HEADS; h++) inv[h] = 1.f / sum[h];
        for (int base = s0; base < s1; base += 32) {
            int i = base + lane;
            int cnt = s1 - base; if (cnt > 32) cnt = 32;
            if (i < s1) {
                int2 c = g_csr[i];
                float4 v = __ldg(reinterpret_cast<const float4*>(escore + c.y * 4));
                s_al[wq][lane * 4 + 0] = __expf(v.x - m[0]) * inv[0];
                s_al[wq][lane * 4 + 1] = __expf(v.y - m[1]) * inv[1];
                s_al[wq][lane * 4 + 2] = __expf(v.z - m[2]) * inv[2];
                s_al[wq][lane * 4 + 3] = __expf(v.w - m[3]) * inv[3];
                s_src[wq][lane] = c.x;
            }
            __syncwarp();
            int j = 0;
            for (; j + 4 <= cnt; j += 4) {
                float a0 = s_al[wq][(j + 0) * 4 + hsel];
                float a1 = s_al[wq][(j + 1) * 4 + hsel];
                float a2 = s_al[wq][(j + 2) * 4 + hsel];
                float a3 = s_al[wq][(j + 3) * 4 + hsel];
                int sj0 = s_src[wq][j + 0];
                int sj1 = s_src[wq][j + 1];
                int sj2 = s_src[wq][j + 2];
                int sj3 = s_src[wq][j + 3];
                float4 x0 = __ldg(reinterpret_cast<const float4*>(xs + sj0 * D2) + lane);
                float4 x1 = __ldg(reinterpret_cast<const float4*>(xs + sj1 * D2) + lane);
                float4 x2 = __ldg(reinterpret_cast<const float4*>(xs + sj2 * D2) + lane);
                float4 x3 = __ldg(reinterpret_cast<const float4*>(xs + sj3 * D2) + lane);
                acc.x += a0 * x0.x + a1 * x1.x + a2 * x2.x + a3 * x3.x;
                acc.y += a0 * x0.y + a1 * x1.y + a2 * x2.y + a3 * x3.y;
                acc.z += a0 * x0.z + a1 * x1.z + a2 * x2.z + a3 * x3.z;
                acc.w += a0 * x0.w + a1 * x1.w + a2 * x2.w + a3 * x3.w;
            }
            for (; j < cnt; j++) {
                float a = s_al[wq][j * 4 + hsel];
                int sj = s_src[wq][j];
                float4 xv = __ldg(reinterpret_cast<const float4*>(xs + sj * D2) + lane);
                acc.x += a * xv.x; acc.y += a * xv.y; acc.z += a * xv.z; acc.w += a * xv.w;
            }
            __syncwarp();
        }
    }
    float4 o4;
    o4.x = acc.x + bv.x; o4.y = acc.y + bv.y; o4.z = acc.z + bv.z; o4.w = acc.w + bv.w;
    if (ELU) {
        o4.x = (o4.x > 0.f) ? o4.x : expm1f(o4.x);
        o4.y = (o4.y > 0.f) ? o4.y : expm1f(o4.y);
        o4.z = (o4.z > 0.f) ? o4.z : expm1f(o4.z);
        o4.w = (o4.w > 0.f) ? o4.w : expm1f(o4.w);
    }
    reinterpret_cast<float4*>(out + n * D2)[lane] = o4;
}

// H=1 gather (final layer, no ELU), 4-way unrolled j-loop
__global__ __launch_bounds__(256) void gat_gather1_kernel(
        const float* __restrict__ xs, const float* __restrict__ escore,
        const float* __restrict__ bias, float* __restrict__ out) {
    __shared__ float s_a[8][32];
    __shared__ int   s_s[8][32];
    int wq = threadIdx.x >> 5;
    int n = (blockIdx.x * 256 + threadIdx.x) >> 5;
    int lane = threadIdx.x & 31;
    if (n >= NN) return;
    int s0 = __ldg(&g_rowptr[n]), s1 = __ldg(&g_rowptr[n + 1]);
    int deg = s1 - s0;
    float bv = __ldg(bias + lane);
    float acc = 0.f;

    if (deg > 0 && deg <= 32) {
        float es = -CUDART_INF_F;
        int src = 0;
        if (lane < deg) {
            int2 c = g_csr[s0 + lane];
            src = c.x;
            es = __ldg(escore + c.y);
        }
        float m = es;
#pragma unroll
        for (int o = 16; o > 0; o >>= 1) m = fmaxf(m, __shfl_xor_sync(0xffffffffu, m, o));
        float p = (lane < deg) ? __expf(es - m) : 0.f;
        float sum = p;
#pragma unroll
        for (int o = 16; o > 0; o >>= 1) sum += __shfl_xor_sync(0xffffffffu, sum, o);
        p *= (1.f / sum);
        if (lane < deg) { s_a[wq][lane] = p; s_s[wq][lane] = src; }
        __syncwarp();
        int j = 0;
        for (; j + 4 <= deg; j += 4) {
            float a0 = s_a[wq][j + 0], a1 = s_a[wq][j + 1], a2 = s_a[wq][j + 2], a3 = s_a[wq][j + 3];
            int sj0 = s_s[wq][j + 0], sj1 = s_s[wq][j + 1], sj2 = s_s[wq][j + 2], sj3 = s_s[wq][j + 3];
            float x0 = __ldg(xs + sj0 * HIDC + lane);
            float x1 = __ldg(xs + sj1 * HIDC + lane);
            float x2 = __ldg(xs + sj2 * HIDC + lane);
            float x3 = __ldg(xs + sj3 * HIDC + lane);
            acc += a0 * x0 + a1 * x1 + a2 * x2 + a3 * x3;
        }
        for (; j < deg; j++)
            acc += s_a[wq][j] * __ldg(xs + s_s[wq][j] * HIDC + lane);
    } else if (deg > 32) {
        float m = -CUDART_INF_F;
        for (int i = s0 + lane; i < s1; i += 32) {
            int2 c = g_csr[i];
            m = fmaxf(m, __ldg(escore + c.y));
        }
#pragma unroll
        for (int o = 16; o > 0; o >>= 1) m = fmaxf(m, __shfl_xor_sync(0xffffffffu, m, o));
        float sum = 0.f;
        for (int i = s0 + lane; i < s1; i += 32) {
            int2 c = g_csr[i];
            sum += __expf(__ldg(escore + c.y) - m);
        }
#pragma unroll
        for (int o = 16; o > 0; o >>= 1) sum += __shfl_xor_sync(0xffffffffu, sum, o);
        float inv = 1.f / sum;
        for (int base = s0; base < s1; base += 32) {
            int i = base + lane;
            int cnt = s1 - base; if (cnt > 32) cnt = 32;
            if (i < s1) {
                int2 c = g_csr[i];
                s_a[wq][lane] = __expf(__ldg(escore + c.y) - m) * inv;
                s_s[wq][lane] = c.x;
            }
            __syncwarp();
            int j = 0;
            for (; j + 4 <= cnt; j += 4) {
                float a0 = s_a[wq][j + 0], a1 = s_a[wq][j + 1], a2 = s_a[wq][j + 2], a3 = s_a[wq][j + 3];
                int sj0 = s_s[wq][j + 0], sj1 = s_s[wq][j + 1], sj2 = s_s[wq][j + 2], sj3 = s_s[wq][j + 3];
                float x0 = __ldg(xs + sj0 * HIDC + lane);
                float x1 = __ldg(xs + sj1 * HIDC + lane);
                float x2 = __ldg(xs + sj2 * HIDC + lane);
                float x3 = __ldg(xs + sj3 * HIDC + lane);
                acc += a0 * x0 + a1 * x1 + a2 * x2 + a3 * x3;
            }
            for (; j < cnt; j++)
                acc += s_a[wq][j] * __ldg(xs + s_s[wq][j] * HIDC + lane);
            __syncwarp();
        }
    }
    out[n * HIDC + lane] = acc + bv;
}

// ---------------- pooling ----------------
__global__ void pool_kernel(const int* __restrict__ batch) {
    int i = blockIdx.x * blockDim.x + threadIdx.x;
    if (i >= NN * HIDC) return;
    int n = i >> 5;
    int c = i & 31;
    int g = batch[n];
    atomicAdd(&g_sums[g * HIDC + c], g_h3[i]);
    if (c == 0) atomicAdd(&g_cnt[g], 1.f);
}

// ---------------- MLP head ----------------
__global__ void mlp_kernel(const float* __restrict__ Wm1, const float* __restrict__ bm1,
                           const float* __restrict__ Wm2, const float* __restrict__ bm2,
                           float* __restrict__ out) {
    __shared__ float emb[HIDC];
    __shared__ float hid[2 * HIDC];
    int g = blockIdx.x;
    int tid = threadIdx.x;   // 64 threads
    if (tid < HIDC) {
        float c = g_cnt[g];
        emb[tid] = g_sums[g * HIDC + tid] / fmaxf(c, 1.f);
    }
    __syncthreads();
    float a = bm1[tid];
#pragma unroll
    for (int k = 0; k < HIDC; k++) a += emb[k] * Wm1[k * (2 * HIDC) + tid];
    hid[tid] = fmaxf(a, 0.f);
    __syncthreads();
    float o = bm2[tid];
#pragma unroll
    for (int k = 0; k < 2 * HIDC; k++) o += hid[k] * Wm2[k * OUTD + tid];
    out[g * OUTD + tid] = o;
}

// ---------------- launch (dual-stream: CSR build overlapped with layer-1 compute) ----------------
extern "C" void kernel_launch(void* const* d_in, const int* in_sizes, int n_in,
                              void* d_out, int out_size) {
    const float* x         = (const float*)d_in[0];
    const int*   edge_src  = (const int*)d_in[1];
    const int*   edge_dst  = (const int*)d_in[2];
    const float* edge_attr = (const float*)d_in[3];
    const int*   batch     = (const int*)d_in[4];
    const float* W1s = (const float*)d_in[5],  *W1d = (const float*)d_in[6],  *W1e = (const float*)d_in[7];
    const float* b1s = (const float*)d_in[8],  *b1d = (const float*)d_in[9];
    const float* att1 = (const float*)d_in[10], *bias1 = (const float*)d_in[11];
    const float* W2s = (const float*)d_in[12], *W2d = (const float*)d_in[13], *W2e = (const float*)d_in[14];
    const float* b2s = (const float*)d_in[15], *b2d = (const float*)d_in[16];
    const float* att2 = (const float*)d_in[17], *bias2 = (const float*)d_in[18];
    const float* W3s = (const float*)d_in[19], *W3d = (const float*)d_in[20], *W3e = (const float*)d_in[21];
    const float* b3s = (const float*)d_in[22], *b3d = (const float*)d_in[23];
    const float* att3 = (const float*)d_in[24], *bias3 = (const float*)d_in[25];
    const float* Wm1 = (const float*)d_in[26], *bm1 = (const float*)d_in[27];
    const float* Wm2 = (const float*)d_in[28], *bm2 = (const float*)d_in[29];
    float* out = (float*)d_out;

    void *p_xs, *p_xd, *p_h1, *p_h2, *p_h3, *p_es;
    cudaGetSymbolAddress(&p_xs, g_xs);
    cudaGetSymbolAddress(&p_xd, g_xd);
    cudaGetSymbolAddress(&p_h1, g_h1);
    cudaGetSymbolAddress(&p_h2, g_h2);
    cudaGetSymbolAddress(&p_h3, g_h3);
    cudaGetSymbolAddress(&p_es, g_escore);
    float* xs = (float*)p_xs; float* xd = (float*)p_xd;
    float* h1 = (float*)p_h1; float* h2 = (float*)p_h2; float* h3 = (float*)p_h3;
    float* es = (float*)p_es;

    // lazily-created side stream + fork/join events (host objects, no device mem)
    static cudaStream_t s2 = nullptr;
    static cudaEvent_t evFork = nullptr, evJoin = nullptr;
    if (s2 == nullptr) {
        cudaStreamCreateWithFlags(&s2, cudaStreamNonBlocking);
        cudaEventCreateWithFlags(&evFork, cudaEventDisableTiming);
        cudaEventCreateWithFlags(&evJoin, cudaEventDisableTiming);
    }

    const int SCORE_BLOCKS = 6400;   // 128-thread blocks
    const int GATHER_BLOCKS = (NN * 32 + 255) / 256;

    // fork: CSR build on side stream, overlapped with linear1 + score4 L1
    cudaEventRecord(evFork, 0);
    cudaStreamWaitEvent(s2, evFork, 0);
    zero_kernel<<<(NN + 255) / 256, 256, 0, s2>>>();
    hist_kernel<<<(EE + 255) / 256, 256, 0, s2>>>(edge_dst);
    scan1_kernel<<<SCAN_NB, SCAN_BLK, 0, s2>>>();
    scan3_kernel<<<(NN + 255) / 256, 256, 0, s2>>>();
    scatter_kernel<<<(EE + 255) / 256, 256, 0, s2>>>(edge_src, edge_dst);
    cudaEventRecord(evJoin, s2);

    // main stream: layer-1 dense + scores (independent of CSR)
    node_linear_kernel<IN_DIM, D2, 16><<<(NN + 15) / 16, D2>>>(x, W1s, W1d, b1s, b1d, xs, xd);
    gat_score4_kernel<<<SCORE_BLOCKS, 128>>>(xs, xd, edge_src, edge_dst, edge_attr, W1e, att1, es);

    // join: gathers need CSR
    cudaStreamWaitEvent(0, evJoin, 0);
    gat_gather4_kernel<true><<<GATHER_BLOCKS, 256>>>(xs, es, bias1, h1);

    // Layer 2
    node_linear_kernel<D2, D2, 32><<<(NN + 31) / 32, D2>>>(h1, W2s, W2d, b2s, b2d, xs, xd);
    gat_score4_kernel<<<SCORE_BLOCKS, 128>>>(xs, xd, edge_src, edge_dst, edge_attr, W2e, att2, es);
    gat_gather4_kernel<true><<<GATHER_BLOCKS, 256>>>(xs, es, bias2, h2);

    // Layer 3 (1 head)
    node_linear_kernel<D2, HIDC, 32><<<(NN + 31) / 32, HIDC>>>(h2, W3s, W3d, b3s, b3d, xs, xd);
    gat_score1_kernel<<<SCORE_BLOCKS, 128>>>(xs, xd, edge_src, edge_dst, edge_attr, W3e, att3, es);
    gat_gather1_kernel<<<GATHER_BLOCKS, 256>>>(xs, es, bias3, h3);

    // Pool + MLP
    pool_kernel<<<(NN * HIDC + 255) / 256, 256>>>(batch);
    mlp_kernel<<<GG, OUTD>>>(Wm1, bm1, Wm2, bm2, out);
}

// round 17
// speedup vs baseline: 1.0310x; 1.0310x over previous
#include <cuda_runtime.h>
#include <cuda_bf16.h>
#include <math_constants.h>
#include <cstdint>

// Problem constants (fixed by dataset)
#define NN     50000
#define EE     800000
#define GG     512
#define IN_DIM 16
#define EDGE_DIM 8
#define HIDC   32
#define OUTD   64
#define HEADS  4
#define D2     (HEADS*HIDC)   // 128

#define SCAN_BLK 1024
#define SCAN_NB  ((NN + SCAN_BLK - 1) / SCAN_BLK)   // 49

typedef unsigned long long u64;

// ---- packed f32x2 helpers (Blackwell: fma.rn.f32x2 etc.) ----
__device__ __forceinline__ u64 pk2(float a, float b) {
    u64 r; asm("mov.b64 %0, {%1, %2};" : "=l"(r) : "f"(a), "f"(b)); return r;
}
__device__ __forceinline__ void upk2(u64 v, float& a, float& b) {
    asm("mov.b64 {%0, %1}, %2;" : "=f"(a), "=f"(b) : "l"(v));
}
__device__ __forceinline__ u64 fma2_(u64 a, u64 b, u64 c) {
    u64 r; asm("fma.rn.f32x2 %0, %1, %2, %3;" : "=l"(r) : "l"(a), "l"(b), "l"(c)); return r;
}
__device__ __forceinline__ u64 add2_(u64 a, u64 b) {
    u64 r; asm("add.rn.f32x2 %0, %1, %2;" : "=l"(r) : "l"(a), "l"(b)); return r;
}
__device__ __forceinline__ u64 mul2_(u64 a, u64 b) {
    u64 r; asm("mul.rn.f32x2 %0, %1, %2;" : "=l"(r) : "l"(a), "l"(b)); return r;
}
__device__ __forceinline__ u64 abs2_(u64 a) {
    u64 r; asm("and.b64 %0, %1, %2;" : "=l"(r) : "l"(a), "l"(0x7FFFFFFF7FFFFFFFULL)); return r;
}

// ---------------- device scratch ----------------
__device__ float g_xs[NN * D2];
__device__ float g_xd[NN * D2];
__device__ float g_h1[NN * D2];
__device__ float g_h2[NN * D2];
__device__ float g_escore[EE * HEADS];   // [eid][h] (float4 per edge when H=4)
__device__ int   g_deg[NN];
__device__ int   g_tmp[SCAN_NB * SCAN_BLK];
__device__ int   g_rowptr[NN + 1];
__device__ int   g_wp[NN];
__device__ int   g_blksum[SCAN_NB + 1];
__device__ int2  g_csr[EE];              // (src, eid) per csr slot
__device__ float g_sums[GG * HIDC];
__device__ float g_cnt[GG];

// ---------------- CSR build ----------------
__global__ void zero_kernel() {
    int i = blockIdx.x * blockDim.x + threadIdx.x;
    if (i < NN) g_deg[i] = 0;
    if (i < GG * HIDC) g_sums[i] = 0.f;
    if (i < GG) g_cnt[i] = 0.f;
}

__global__ void hist_kernel(const int* __restrict__ dst) {
    int e = blockIdx.x * blockDim.x + threadIdx.x;
    if (e < EE) atomicAdd(&g_deg[dst[e]], 1);
}

__global__ void scan1_kernel() {
    __shared__ int sm[SCAN_BLK];
    int tid = threadIdx.x;
    int i = blockIdx.x * SCAN_BLK + tid;
    int v = (i < NN) ? g_deg[i] : 0;
    sm[tid] = v;
    __syncthreads();
    for (int o = 1; o < SCAN_BLK; o <<= 1) {
        int t = (tid >= o) ? sm[tid - o] : 0;
        __syncthreads();
        sm[tid] += t;
        __syncthreads();
    }
    g_tmp[blockIdx.x * SCAN_BLK + tid] = sm[tid] - v;
    if (tid == SCAN_BLK - 1) g_blksum[blockIdx.x] = sm[tid];
}

// scan3 folds the cross-block prefix (each 256-block sits inside one 1024-chunk)
__global__ void scan3_kernel() {
    __shared__ int s_off;
    int blk = (blockIdx.x * 256) / SCAN_BLK;
    if (threadIdx.x == 0) {
        int run = 0;
        for (int b = 0; b < blk; b++) run += g_blksum[b];
        s_off = run;
    }
    __syncthreads();
    int i = blockIdx.x * 256 + threadIdx.x;
    if (i < NN) {
        int v = g_tmp[i] + s_off;
        g_rowptr[i] = v;
        g_wp[i] = v;
    }
    if (i == 0) g_rowptr[NN] = EE;
}

__global__ void scatter_kernel(const int* __restrict__ src, const int* __restrict__ dst) {
    int e = blockIdx.x * blockDim.x + threadIdx.x;
    if (e < EE) {
        int d = dst[e];
        int pos = atomicAdd(&g_wp[d], 1);
        g_csr[pos] = make_int2(src[e], e);
    }
}

// ---------------- node linear (packed f32x2, padded smem) ----------------
template<int DIN, int DOUT, int TN>
__global__ __launch_bounds__(DOUT) void node_linear_kernel(
        const float* __restrict__ x,
        const float* __restrict__ Ws, const float* __restrict__ Wd,
        const float* __restrict__ bs, const float* __restrict__ bd,
        float* __restrict__ xs, float* __restrict__ xd) {
    __shared__ float xsm[DIN][TN + 2];
    const int n0 = blockIdx.x * TN;
    const int tid = threadIdx.x;
    for (int i = tid; i < TN * DIN; i += DOUT) {
        int t = i / DIN, k = i - t * DIN;
        int n = n0 + t;
        xsm[k][t] = (n < NN) ? x[n * DIN + k] : 0.f;
    }
    __syncthreads();

    u64 accs[TN / 2], accd[TN / 2];
#pragma unroll
    for (int p = 0; p < TN / 2; p++) { accs[p] = 0ull; accd[p] = 0ull; }

#pragma unroll 4
    for (int k = 0; k < DIN; k++) {
        float wsv = __ldg(Ws + k * DOUT + tid);
        float wdv = __ldg(Wd + k * DOUT + tid);
        u64 ws2 = pk2(wsv, wsv);
        u64 wd2 = pk2(wdv, wdv);
        const u64* xp = reinterpret_cast<const u64*>(&xsm[k][0]);
#pragma unroll
        for (int p = 0; p < TN / 2; p++) {
            u64 xv = xp[p];
            accs[p] = fma2_(xv, ws2, accs[p]);
            accd[p] = fma2_(xv, wd2, accd[p]);
        }
    }
    float bsv = __ldg(bs + tid), bdv = __ldg(bd + tid);
#pragma unroll
    for (int p = 0; p < TN / 2; p++) {
        float s_lo, s_hi, d_lo, d_hi;
        upk2(accs[p], s_lo, s_hi);
        upk2(accd[p], d_lo, d_hi);
        int n = n0 + 2 * p;
        if (n < NN) {
            xs[n * DOUT + tid] = s_lo + bsv;
            xd[n * DOUT + tid] = d_lo + bdv;
        }
        if (n + 1 < NN) {
            xs[(n + 1) * DOUT + tid] = s_hi + bsv;
            xd[(n + 1) * DOUT + tid] = d_hi + bdv;
        }
    }
}

// ---------------- GATv2 scores: warp per edge PAIR, packed f32x2 math (FROZEN) ----------------
__global__ __launch_bounds__(128, 5) void gat_score4_kernel(
        const float* __restrict__ xs, const float* __restrict__ xd,
        const int* __restrict__ esrc, const int* __restrict__ edst,
        const float* __restrict__ eattr,
        const float* __restrict__ We, const float* __restrict__ att,
        float* __restrict__ escore) {
    __shared__ float sWe[EDGE_DIM * D2];
    for (int i = threadIdx.x; i < EDGE_DIM * D2; i += 128) sWe[i] = We[i];
    __syncthreads();

    int lane = threadIdx.x & 31;
    int g = lane >> 3;          // head
    int q = lane & 7;           // channel quad
    int col0 = g * 32 + q * 4;

    u64 we2[2][EDGE_DIM];
    u64 att2[2];
#pragma unroll
    for (int p = 0; p < 2; p++) {
#pragma unroll
        for (int k = 0; k < EDGE_DIM; k++)
            we2[p][k] = pk2(sWe[k * D2 + col0 + 2 * p], sWe[k * D2 + col0 + 2 * p + 1]);
        att2[p] = pk2(__ldg(att + col0 + 2 * p), __ldg(att + col0 + 2 * p + 1));
    }
    const u64 C06 = pk2(0.6f, 0.6f);
    const u64 C04 = pk2(0.4f, 0.4f);

    int warpId = (blockIdx.x * 128 + threadIdx.x) >> 5;
    int stride = (gridDim.x * 128) >> 5;
    int step = 2 * stride;

    int e0 = warpId, e1 = warpId + stride;
    int s0 = 0, d0 = 0, s1 = 0, d1 = 0;
    if (e0 < EE) { s0 = __ldg(esrc + e0); d0 = __ldg(edst + e0); }
    if (e1 < EE) { s1 = __ldg(esrc + e1); d1 = __ldg(edst + e1); }

    while (e0 < EE) {
        bool v1 = (e1 < EE);
        const float4* ap0 = reinterpret_cast<const float4*>(eattr + e0 * EDGE_DIM);
        float4 a00 = __ldg(ap0), a01 = __ldg(ap0 + 1);
        float4 xs0 = __ldg(reinterpret_cast<const float4*>(xs + s0 * D2 + col0));
        float4 xd0 = __ldg(reinterpret_cast<const float4*>(xd + d0 * D2 + col0));
        float4 a10 = make_float4(0,0,0,0), a11 = a10, xs1 = a10, xd1 = a10;
        if (v1) {
            const float4* ap1 = reinterpret_cast<const float4*>(eattr + e1 * EDGE_DIM);
            a10 = __ldg(ap1); a11 = __ldg(ap1 + 1);
            xs1 = __ldg(reinterpret_cast<const float4*>(xs + s1 * D2 + col0));
            xd1 = __ldg(reinterpret_cast<const float4*>(xd + d1 * D2 + col0));
        }
        int ne0 = e0 + step, ne1 = e1 + step;
        int ns0 = 0, nd0 = 0, ns1 = 0, nd1 = 0;
        if (ne0 < EE) { ns0 = __ldg(esrc + ne0); nd0 = __ldg(edst + ne0); }
        if (ne1 < EE) { ns1 = __ldg(esrc + ne1); nd1 = __ldg(edst + ne1); }

        // edge 0 (packed)
        {
            u64 ak[8] = { pk2(a00.x,a00.x), pk2(a00.y,a00.y), pk2(a00.z,a00.z), pk2(a00.w,a00.w),
                          pk2(a01.x,a01.x), pk2(a01.y,a01.y), pk2(a01.z,a01.z), pk2(a01.w,a01.w) };
            u64 xsp[2] = { pk2(xs0.x, xs0.y), pk2(xs0.z, xs0.w) };
            u64 xdp[2] = { pk2(xd0.x, xd0.y), pk2(xd0.z, xd0.w) };
            u64 sc2 = 0ull;
#pragma unroll
            for (int p = 0; p < 2; p++) {
                u64 ea2 = mul2_(ak[0], we2[p][0]);
#pragma unroll
                for (int k = 1; k < EDGE_DIM; k++) ea2 = fma2_(ak[k], we2[p][k], ea2);
                u64 z2 = add2_(add2_(xsp[p], xdp[p]), ea2);
                u64 r2 = fma2_(z2, C06, mul2_(abs2_(z2), C04));
                sc2 = fma2_(r2, att2[p], sc2);
            }
            float lo, hi; upk2(sc2, lo, hi);
            float pr = lo + hi;
            pr += __shfl_xor_sync(0xffffffffu, pr, 4);
            pr += __shfl_xor_sync(0xffffffffu, pr, 2);
            pr += __shfl_xor_sync(0xffffffffu, pr, 1);
            if (q == 0) escore[e0 * 4 + g] = pr;
        }
        // edge 1 (independent chain)
        if (v1) {
            u64 ak[8] = { pk2(a10.x,a10.x), pk2(a10.y,a10.y), pk2(a10.z,a10.z), pk2(a10.w,a10.w),
                          pk2(a11.x,a11.x), pk2(a11.y,a11.y), pk2(a11.z,a11.z), pk2(a11.w,a11.w) };
            u64 xsp[2] = { pk2(xs1.x, xs1.y), pk2(xs1.z, xs1.w) };
            u64 xdp[2] = { pk2(xd1.x, xd1.y), pk2(xd1.z, xd1.w) };
            u64 sc2 = 0ull;
#pragma unroll
            for (int p = 0; p < 2; p++) {
                u64 ea2 = mul2_(ak[0], we2[p][0]);
#pragma unroll
                for (int k = 1; k < EDGE_DIM; k++) ea2 = fma2_(ak[k], we2[p][k], ea2);
                u64 z2 = add2_(add2_(xsp[p], xdp[p]), ea2);
                u64 r2 = fma2_(z2, C06, mul2_(abs2_(z2), C04));
                sc2 = fma2_(r2, att2[p], sc2);
            }
            float lo, hi; upk2(sc2, lo, hi);
            float pr = lo + hi;
            pr += __shfl_xor_sync(0xffffffffu, pr, 4);
            pr += __shfl_xor_sync(0xffffffffu, pr, 2);
            pr += __shfl_xor_sync(0xffffffffu, pr, 1);
            if (q == 0) escore[e1 * 4 + g] = pr;
        }

        e0 = ne0; e1 = ne1;
        s0 = ns0; d0 = nd0; s1 = ns1; d1 = nd1;
    }
}

// H=1: 4 edges per warp, pipelined src/dst prefetch, folded leaky
__global__ __launch_bounds__(128) void gat_score1_kernel(
        const float* __restrict__ xs, const float* __restrict__ xd,
        const int* __restrict__ esrc, const int* __restrict__ edst,
        const float* __restrict__ eattr,
        const float* __restrict__ We, const float* __restrict__ att,
        float* __restrict__ escore) {
    int lane = threadIdx.x & 31;
    int g = lane >> 3;
    int q = lane & 7;
    int col0 = q * 4;

    float we_r[4][EDGE_DIM];
    float a06[4], a04[4];
#pragma unroll
    for (int c = 0; c < 4; c++) {
#pragma unroll
        for (int k = 0; k < EDGE_DIM; k++) we_r[c][k] = __ldg(We + k * HIDC + col0 + c);
        float av = __ldg(att + col0 + c);
        a06[c] = 0.6f * av;
        a04[c] = 0.4f * av;
    }

    int warpId = (blockIdx.x * 128 + threadIdx.x) >> 5;
    int nWarps = (gridDim.x * 128) >> 5;
    int step = nWarps * 4;

    int eb = warpId * 4;
    int e = eb + g;
    int s = 0, d = 0;
    if (e < EE) { s = __ldg(esrc + e); d = __ldg(edst + e); }

    while (eb < EE) {
        bool valid = (e < EE);
        float4 a0 = make_float4(0,0,0,0), a1 = a0, xsv = a0, xdv = a0;
        if (valid) {
            const float4* ap = reinterpret_cast<const float4*>(eattr + e * EDGE_DIM);
            a0 = __ldg(ap); a1 = __ldg(ap + 1);
            xsv = __ldg(reinterpret_cast<const float4*>(xs + s * HIDC + col0));
            xdv = __ldg(reinterpret_cast<const float4*>(xd + d * HIDC + col0));
        }
        int neb = eb + step;
        int ne = neb + g;
        int ns = 0, nd = 0;
        if (ne < EE) { ns = __ldg(esrc + ne); nd = __ldg(edst + ne); }

        if (valid) {
            const float* xsa = &xsv.x;
            const float* xda = &xdv.x;
            float pr = 0.f;
#pragma unroll
            for (int c = 0; c < 4; c++) {
                float ea = a0.x * we_r[c][0] + a0.y * we_r[c][1] + a0.z * we_r[c][2] + a0.w * we_r[c][3]
                         + a1.x * we_r[c][4] + a1.y * we_r[c][5] + a1.z * we_r[c][6] + a1.w * we_r[c][7];
                float z = xsa[c] + xda[c] + ea;
                pr = fmaf(a06[c], z, fmaf(a04[c], fabsf(z), pr));
            }
            pr += __shfl_xor_sync(0xffffffffu, pr, 4);
            pr += __shfl_xor_sync(0xffffffffu, pr, 2);
            pr += __shfl_xor_sync(0xffffffffu, pr, 1);
            if (q == 0) escore[e] = pr;
        }
        eb = neb; e = ne; s = ns; d = nd;
    }
}

// ---------------- softmax + gather: warp per node, float4-row (R15 proven) ----------------
template<bool ELU>
__global__ __launch_bounds__(256) void gat_gather4_kernel(
        const float* __restrict__ xs, const float* __restrict__ escore,
        const float* __restrict__ bias, float* __restrict__ out) {
    __shared__ float s_al[8][32 * 4];   // [warp][j*4 + h]
    __shared__ int   s_src[8][32];
    int wq = threadIdx.x >> 5;
    int n = (blockIdx.x * 256 + threadIdx.x) >> 5;
    int lane = threadIdx.x & 31;
    if (n >= NN) return;
    int s0 = __ldg(&g_rowptr[n]), s1 = __ldg(&g_rowptr[n + 1]);
    int deg = s1 - s0;
    int hsel = lane >> 3;   // head owning my channel quad

    float4 bv = __ldg(reinterpret_cast<const float4*>(bias) + lane);
    float4 acc = make_float4(0.f, 0.f, 0.f, 0.f);

    if (deg > 0 && deg <= 32) {
        float es[HEADS];
        int src = 0;
#pragma unroll
        for (int h = 0; h < HEADS; h++) es[h] = -CUDART_INF_F;
        if (lane < deg) {
            int2 c = g_csr[s0 + lane];
            src = c.x;
            float4 v = __ldg(reinterpret_cast<const float4*>(escore + c.y * 4));
            es[0] = v.x; es[1] = v.y; es[2] = v.z; es[3] = v.w;
        }
        float m[HEADS];
#pragma unroll
        for (int h = 0; h < HEADS; h++) m[h] = es[h];
#pragma unroll
        for (int o = 16; o > 0; o >>= 1)
#pragma unroll
            for (int h = 0; h < HEADS; h++) m[h] = fmaxf(m[h], __shfl_xor_sync(0xffffffffu, m[h], o));
        float p[HEADS], sum[HEADS];
#pragma unroll
        for (int h = 0; h < HEADS; h++) {
            p[h] = (lane < deg) ? __expf(es[h] - m[h]) : 0.f;
            sum[h] = p[h];
        }
#pragma unroll
        for (int o = 16; o > 0; o >>= 1)
#pragma unroll
            for (int h = 0; h < HEADS; h++) sum[h] += __shfl_xor_sync(0xffffffffu, sum[h], o);
        if (lane < deg) {
#pragma unroll
            for (int h = 0; h < HEADS; h++) s_al[wq][lane * 4 + h] = p[h] / sum[h];
            s_src[wq][lane] = src;
        }
        __syncwarp();
        for (int j = 0; j < deg; j++) {
            float a = s_al[wq][j * 4 + hsel];
            int sj = s_src[wq][j];
            float4 xv = __ldg(reinterpret_cast<const float4*>(xs + sj * D2) + lane);
            acc.x += a * xv.x; acc.y += a * xv.y; acc.z += a * xv.z; acc.w += a * xv.w;
        }
    } else if (deg > 32) {
        float m[HEADS];
#pragma unroll
        for (int h = 0; h < HEADS; h++) m[h] = -CUDART_INF_F;
        for (int i = s0 + lane; i < s1; i += 32) {
            int2 c = g_csr[i];
            float4 v = __ldg(reinterpret_cast<const float4*>(escore + c.y * 4));
            m[0] = fmaxf(m[0], v.x); m[1] = fmaxf(m[1], v.y);
            m[2] = fmaxf(m[2], v.z); m[3] = fmaxf(m[3], v.w);
        }
#pragma unroll
        for (int o = 16; o > 0; o >>= 1)
#pragma unroll
            for (int h = 0; h < HEADS; h++) m[h] = fmaxf(m[h], __shfl_xor_sync(0xffffffffu, m[h], o));
        float sum[HEADS] = {0.f, 0.f, 0.f, 0.f};
        for (int i = s0 + lane; i < s1; i += 32) {
            int2 c = g_csr[i];
            float4 v = __ldg(reinterpret_cast<const float4*>(escore + c.y * 4));
            sum[0] += __expf(v.x - m[0]); sum[1] += __expf(v.y - m[1]);
            sum[2] += __expf(v.z - m[2]); sum[3] += __expf(v.w - m[3]);
        }
#pragma unroll
        for (int o = 16; o > 0; o >>= 1)
#pragma unroll
            for (int h = 0; h < HEADS; h++) sum[h] += __shfl_xor_sync(0xffffffffu, sum[h], o);
        float inv[HEADS];
#pragma unroll
        for (int h = 0; h < HEADS; h++) inv[h] = 1.f / sum[h];
        for (int base = s0; base < s1; base += 32) {
            int i = base + lane;
            int cnt = s1 - base; if (cnt > 32) cnt = 32;
            if (i < s1) {
                int2 c = g_csr[i];
                float4 v = __ldg(reinterpret_cast<const float4*>(escore + c.y * 4));
                s_al[wq][lane * 4 + 0] = __expf(v.x - m[0]) * inv[0];
                s_al[wq][lane * 4 + 1] = __expf(v.y - m[1]) * inv[1];
                s_al[wq][lane * 4 + 2] = __expf(v.z - m[2]) * inv[2];
                s_al[wq][lane * 4 + 3] = __expf(v.w - m[3]) * inv[3];
                s_src[wq][lane] = c.x;
            }
            __syncwarp();
            for (int j = 0; j < cnt; j++) {
                float a = s_al[wq][j * 4 + hsel];
                int sj = s_src[wq][j];
                float4 xv = __ldg(reinterpret_cast<const float4*>(xs + sj * D2) + lane);
                acc.x += a * xv.x; acc.y += a * xv.y; acc.z += a * xv.z; acc.w += a * xv.w;
            }
            __syncwarp();
        }
    }
    float4 o4;
    o4.x = acc.x + bv.x; o4.y = acc.y + bv.y; o4.z = acc.z + bv.z; o4.w = acc.w + bv.w;
    if (ELU) {
        o4.x = (o4.x > 0.f) ? o4.x : expm1f(o4.x);
        o4.y = (o4.y > 0.f) ? o4.y : expm1f(o4.y);
        o4.z = (o4.z > 0.f) ? o4.z : expm1f(o4.z);
        o4.w = (o4.w > 0.f) ? o4.w : expm1f(o4.w);
    }
    reinterpret_cast<float4*>(out + n * D2)[lane] = o4;
}

// H=1 gather (final layer, no ELU) with FUSED mean-pool accumulation:
// writes directly into g_sums[batch[n]] / g_cnt instead of materializing h3.
__global__ __launch_bounds__(256) void gat_gather1_pool_kernel(
        const float* __restrict__ xs, const float* __restrict__ escore,
        const float* __restrict__ bias, const int* __restrict__ batch) {
    int n = (blockIdx.x * 256 + threadIdx.x) >> 5;
    int lane = threadIdx.x & 31;
    if (n >= NN) return;
    int s0 = __ldg(&g_rowptr[n]), s1 = __ldg(&g_rowptr[n + 1]);
    int deg = s1 - s0;
    float bv = __ldg(bias + lane);
    float acc = 0.f;

    if (deg > 0 && deg <= 32) {
        float es = -CUDART_INF_F;
        int src = 0;
        if (lane < deg) {
            int2 c = g_csr[s0 + lane];
            src = c.x;
            es = __ldg(escore + c.y);
        }
        float m = es;
#pragma unroll
        for (int o = 16; o > 0; o >>= 1) m = fmaxf(m, __shfl_xor_sync(0xffffffffu, m, o));
        float p = (lane < deg) ? __expf(es - m) : 0.f;
        float sum = p;
#pragma unroll
        for (int o = 16; o > 0; o >>= 1) sum += __shfl_xor_sync(0xffffffffu, sum, o);
        p *= (1.f / sum);
        for (int j = 0; j < deg; j++) {
            int sj = __shfl_sync(0xffffffffu, src, j);
            float a = __shfl_sync(0xffffffffu, p, j);
            acc += a * __ldg(xs + sj * HIDC + lane);
        }
    } else if (deg > 32) {
        float m = -CUDART_INF_F;
        for (int i = s0 + lane; i < s1; i += 32) {
            int2 c = g_csr[i];
            m = fmaxf(m, __ldg(escore + c.y));
        }
#pragma unroll
        for (int o = 16; o > 0; o >>= 1) m = fmaxf(m, __shfl_xor_sync(0xffffffffu, m, o));
        float sum = 0.f;
        for (int i = s0 + lane; i < s1; i += 32) {
            int2 c = g_csr[i];
            sum += __expf(__ldg(escore + c.y) - m);
        }
#pragma unroll
        for (int o = 16; o > 0; o >>= 1) sum += __shfl_xor_sync(0xffffffffu, sum, o);
        float inv = 1.f / sum;
        for (int base = s0; base < s1; base += 32) {
            int i = base + lane;
            float p = 0.f;
            int src = 0;
            if (i < s1) {
                int2 c = g_csr[i];
                src = c.x;
                p = __expf(__ldg(escore + c.y) - m) * inv;
            }
            int cnt = s1 - base; if (cnt > 32) cnt = 32;
            for (int j = 0; j < cnt; j++) {
                int sj = __shfl_sync(0xffffffffu, src, j);
                float a = __shfl_sync(0xffffffffu, p, j);
                acc += a * __ldg(xs + sj * HIDC + lane);
            }
        }
    }
    // fused mean-pool accumulation (batch[n] is warp-uniform)
    int gidx = __ldg(batch + n);
    atomicAdd(&g_sums[gidx * HIDC + lane], acc + bv);
    if (lane == 0) atomicAdd(&g_cnt[gidx], 1.f);
}

// ---------------- MLP head ----------------
__global__ void mlp_kernel(const float* __restrict__ Wm1, const float* __restrict__ bm1,
                           const float* __restrict__ Wm2, const float* __restrict__ bm2,
                           float* __restrict__ out) {
    __shared__ float emb[HIDC];
    __shared__ float hid[2 * HIDC];
    int g = blockIdx.x;
    int tid = threadIdx.x;   // 64 threads
    if (tid < HIDC) {
        float c = g_cnt[g];
        emb[tid] = g_sums[g * HIDC + tid] / fmaxf(c, 1.f);
    }
    __syncthreads();
    float a = bm1[tid];
#pragma unroll
    for (int k = 0; k < HIDC; k++) a += emb[k] * Wm1[k * (2 * HIDC) + tid];
    hid[tid] = fmaxf(a, 0.f);
    __syncthreads();
    float o = bm2[tid];
#pragma unroll
    for (int k = 0; k < 2 * HIDC; k++) o += hid[k] * Wm2[k * OUTD + tid];
    out[g * OUTD + tid] = o;
}

// ---------------- launch (dual-stream: CSR build overlapped with layer-1 compute) ----------------
extern "C" void kernel_launch(void* const* d_in, const int* in_sizes, int n_in,
                              void* d_out, int out_size) {
    const float* x         = (const float*)d_in[0];
    const int*   edge_src  = (const int*)d_in[1];
    const int*   edge_dst  = (const int*)d_in[2];
    const float* edge_attr = (const float*)d_in[3];
    const int*   batch     = (const int*)d_in[4];
    const float* W1s = (const float*)d_in[5],  *W1d = (const float*)d_in[6],  *W1e = (const float*)d_in[7];
    const float* b1s = (const float*)d_in[8],  *b1d = (const float*)d_in[9];
    const float* att1 = (const float*)d_in[10], *bias1 = (const float*)d_in[11];
    const float* W2s = (const float*)d_in[12], *W2d = (const float*)d_in[13], *W2e = (const float*)d_in[14];
    const float* b2s = (const float*)d_in[15], *b2d = (const float*)d_in[16];
    const float* att2 = (const float*)d_in[17], *bias2 = (const float*)d_in[18];
    const float* W3s = (const float*)d_in[19], *W3d = (const float*)d_in[20], *W3e = (const float*)d_in[21];
    const float* b3s = (const float*)d_in[22], *b3d = (const float*)d_in[23];
    const float* att3 = (const float*)d_in[24], *bias3 = (const float*)d_in[25];
    const float* Wm1 = (const float*)d_in[26], *bm1 = (const float*)d_in[27];
    const float* Wm2 = (const float*)d_in[28], *bm2 = (const float*)d_in[29];
    float* out = (float*)d_out;

    void *p_xs, *p_xd, *p_h1, *p_h2, *p_es;
    cudaGetSymbolAddress(&p_xs, g_xs);
    cudaGetSymbolAddress(&p_xd, g_xd);
    cudaGetSymbolAddress(&p_h1, g_h1);
    cudaGetSymbolAddress(&p_h2, g_h2);
    cudaGetSymbolAddress(&p_es, g_escore);
    float* xs = (float*)p_xs; float* xd = (float*)p_xd;
    float* h1 = (float*)p_h1; float* h2 = (float*)p_h2;
    float* es = (float*)p_es;

    // lazily-created side stream + fork/join events (host objects, no device mem)
    static cudaStream_t s2 = nullptr;
    static cudaEvent_t evFork = nullptr, evJoin = nullptr;
    if (s2 == nullptr) {
        cudaStreamCreateWithFlags(&s2, cudaStreamNonBlocking);
        cudaEventCreateWithFlags(&evFork, cudaEventDisableTiming);
        cudaEventCreateWithFlags(&evJoin, cudaEventDisableTiming);
    }

    const int SCORE_BLOCKS = 6400;   // 128-thread blocks
    const int GATHER_BLOCKS = (NN * 32 + 255) / 256;

    // fork: CSR build on side stream, overlapped with linear1 + score4 L1
    cudaEventRecord(evFork, 0);
    cudaStreamWaitEvent(s2, evFork, 0);
    zero_kernel<<<(NN + 255) / 256, 256, 0, s2>>>();
    hist_kernel<<<(EE + 255) / 256, 256, 0, s2>>>(edge_dst);
    scan1_kernel<<<SCAN_NB, SCAN_BLK, 0, s2>>>();
    scan3_kernel<<<(NN + 255) / 256, 256, 0, s2>>>();
    scatter_kernel<<<(EE + 255) / 256, 256, 0, s2>>>(edge_src, edge_dst);
    cudaEventRecord(evJoin, s2);

    // main stream: layer-1 dense + scores (independent of CSR)
    node_linear_kernel<IN_DIM, D2, 16><<<(NN + 15) / 16, D2>>>(x, W1s, W1d, b1s, b1d, xs, xd);
    gat_score4_kernel<<<SCORE_BLOCKS, 128>>>(xs, xd, edge_src, edge_dst, edge_attr, W1e, att1, es);

    // join: gathers need CSR
    cudaStreamWaitEvent(0, evJoin, 0);
    gat_gather4_kernel<true><<<GATHER_BLOCKS, 256>>>(xs, es, bias1, h1);

    // Layer 2
    node_linear_kernel<D2, D2, 32><<<(NN + 31) / 32, D2>>>(h1, W2s, W2d, b2s, b2d, xs, xd);
    gat_score4_kernel<<<SCORE_BLOCKS, 128>>>(xs, xd, edge_src, edge_dst, edge_attr, W2e, att2, es);
    gat_gather4_kernel<true><<<GATHER_BLOCKS, 256>>>(xs, es, bias2, h2);

    // Layer 3 (1 head) with fused pooling
    node_linear_kernel<D2, HIDC, 32><<<(NN + 31) / 32, HIDC>>>(h2, W3s, W3d, b3s, b3d, xs, xd);
    gat_score1_kernel<<<SCORE_BLOCKS, 128>>>(xs, xd, edge_src, edge_dst, edge_attr, W3e, att3, es);
    gat_gather1_pool_kernel<<<GATHER_BLOCKS, 256>>>(xs, es, bias3, batch);

    // MLP head
    mlp_kernel<<<GG, OUTD>>>(Wm1, bm1, Wm2, bm2, out);
}